// round 1
// baseline (speedup 1.0000x reference)
#include <cuda_runtime.h>
#include <math.h>

// ---------------- problem constants (fixed instance) ----------------
#define B_      2
#define S_      4096
#define IN_DIM_ 1280
#define D_      768
#define H_      12
#define HD_     64
#define BS_     64
#define NB_     64       // S_/BS_
#define FF_     3072
#define L_      12
#define M_      (B_*S_)  // 8192
#define TGT_    1024

// ---------------- device scratch (allocation-free) ----------------
__device__ float g_h  [M_*D_];
__device__ float g_q  [M_*D_];
__device__ float g_k  [M_*D_];
__device__ float g_v  [M_*D_];
__device__ float g_ctx[M_*D_];
__device__ float g_t  [M_*D_];
__device__ float g_ff [M_*FF_];
__device__ float g_c1 [B_*512];

// ---------------- helpers ----------------
__device__ __forceinline__ float gelu_new(float x) {
    float x3 = x * x * x;
    return 0.5f * x * (1.0f + tanhf(0.7978845608028654f * (x + 0.044715f * x3)));
}

__device__ __forceinline__ void block_reduce_2(float& s1, float& s2) {
#pragma unroll
    for (int o = 16; o > 0; o >>= 1) {
        s1 += __shfl_xor_sync(0xffffffffu, s1, o);
        s2 += __shfl_xor_sync(0xffffffffu, s2, o);
    }
    __shared__ float sh1[8], sh2[8];
    int w = threadIdx.x >> 5;
    if ((threadIdx.x & 31) == 0) { sh1[w] = s1; sh2[w] = s2; }
    __syncthreads();
    float a = 0.f, b = 0.f;
#pragma unroll
    for (int i = 0; i < 8; i++) { a += sh1[i]; b += sh2[i]; }
    s1 = a; s2 = b;
}

// ---------------- SGEMM: C = A(MxK) @ W(KxN) + bias, optional GELU ----------------
// 128x128 tile, kt=8, 256 threads, 8x8 micro-tile, register prefetch.
// Requires M%128==0, N%128==0, K%8==0, N%4==0.
template<bool GELU>
__global__ void __launch_bounds__(256)
gemm_bias_k(const float* __restrict__ A, const float* __restrict__ W,
            const float* __restrict__ bias, float* __restrict__ C,
            int M, int N, int K)
{
    __shared__ float As[8][128];
    __shared__ float Bs[8][128];
    const int tid  = threadIdx.x;
    const int row0 = blockIdx.y * 128;
    const int col0 = blockIdx.x * 128;

    const int arow = tid >> 1;
    const int acol = (tid & 1) << 2;
    const int wrow = tid >> 5;
    const int wcol = (tid & 31) << 2;

    const float* Ag = A + (size_t)(row0 + arow) * K + acol;
    const float* Wg = W + (size_t)wrow * N + col0 + wcol;

    float4 a4 = *(const float4*)Ag;
    float4 b4 = *(const float4*)Wg;

    float acc[8][8];
#pragma unroll
    for (int i = 0; i < 8; i++)
#pragma unroll
        for (int j = 0; j < 8; j++) acc[i][j] = 0.f;

    const int ty = tid >> 4;
    const int tx = tid & 15;

    for (int kt = 0; kt < K; kt += 8) {
        As[acol + 0][arow] = a4.x;
        As[acol + 1][arow] = a4.y;
        As[acol + 2][arow] = a4.z;
        As[acol + 3][arow] = a4.w;
        *(float4*)&Bs[wrow][wcol] = b4;
        __syncthreads();
        if (kt + 8 < K) {
            a4 = *(const float4*)(Ag + kt + 8);
            b4 = *(const float4*)(Wg + (size_t)(kt + 8) * N);
        }
#pragma unroll
        for (int kk = 0; kk < 8; kk++) {
            float4 af0 = *(const float4*)&As[kk][ty * 8];
            float4 af1 = *(const float4*)&As[kk][ty * 8 + 4];
            float4 bf0 = *(const float4*)&Bs[kk][tx * 8];
            float4 bf1 = *(const float4*)&Bs[kk][tx * 8 + 4];
            float a_[8] = {af0.x, af0.y, af0.z, af0.w, af1.x, af1.y, af1.z, af1.w};
            float b_[8] = {bf0.x, bf0.y, bf0.z, bf0.w, bf1.x, bf1.y, bf1.z, bf1.w};
#pragma unroll
            for (int i = 0; i < 8; i++)
#pragma unroll
                for (int j = 0; j < 8; j++)
                    acc[i][j] = fmaf(a_[i], b_[j], acc[i][j]);
        }
        __syncthreads();
    }

#pragma unroll
    for (int i = 0; i < 8; i++) {
        int r = row0 + ty * 8 + i;
        float* Cp = C + (size_t)r * N + col0 + tx * 8;
#pragma unroll
        for (int j = 0; j < 8; j += 4) {
            float4 v;
            v.x = acc[i][j + 0] + bias[col0 + tx * 8 + j + 0];
            v.y = acc[i][j + 1] + bias[col0 + tx * 8 + j + 1];
            v.z = acc[i][j + 2] + bias[col0 + tx * 8 + j + 2];
            v.w = acc[i][j + 3] + bias[col0 + tx * 8 + j + 3];
            if (GELU) {
                v.x = gelu_new(v.x); v.y = gelu_new(v.y);
                v.z = gelu_new(v.z); v.w = gelu_new(v.w);
            }
            *(float4*)(Cp + j) = v;
        }
    }
}

// ---------------- embedding add + LN: h = LN(t + pos[s] + tok) ----------------
__global__ void emb_ln_k(const float* __restrict__ t, const float* __restrict__ pos,
                         const float* __restrict__ tok, const float* __restrict__ g,
                         const float* __restrict__ be, float* __restrict__ h)
{
    int row = blockIdx.x;
    int s = row & (S_ - 1);
    size_t off = (size_t)row * D_;
    int tid = threadIdx.x;
    float x[3];
#pragma unroll
    for (int e = 0; e < 3; e++) {
        int d = tid + e * 256;
        x[e] = t[off + d] + pos[(size_t)s * D_ + d] + tok[d];
    }
    float s1 = x[0] + x[1] + x[2];
    float s2 = x[0]*x[0] + x[1]*x[1] + x[2]*x[2];
    block_reduce_2(s1, s2);
    float mean = s1 * (1.0f / 768.0f);
    float var  = s2 * (1.0f / 768.0f) - mean * mean;
    float rs = rsqrtf(var + 1e-12f);
#pragma unroll
    for (int e = 0; e < 3; e++) {
        int d = tid + e * 256;
        h[off + d] = (x[e] - mean) * rs * g[d] + be[d];
    }
}

// ---------------- residual + LN in place: h = LN(h + t) ----------------
__global__ void ln_res_k(float* __restrict__ h, const float* __restrict__ t,
                         const float* __restrict__ g, const float* __restrict__ be)
{
    int row = blockIdx.x;
    size_t off = (size_t)row * D_;
    int tid = threadIdx.x;
    float x[3];
#pragma unroll
    for (int e = 0; e < 3; e++) {
        int d = tid + e * 256;
        x[e] = h[off + d] + t[off + d];
    }
    float s1 = x[0] + x[1] + x[2];
    float s2 = x[0]*x[0] + x[1]*x[1] + x[2]*x[2];
    block_reduce_2(s1, s2);
    float mean = s1 * (1.0f / 768.0f);
    float var  = s2 * (1.0f / 768.0f) - mean * mean;
    float rs = rsqrtf(var + 1e-12f);
#pragma unroll
    for (int e = 0; e < 3; e++) {
        int d = tid + e * 256;
        h[off + d] = (x[e] - mean) * rs * g[d] + be[d];
    }
}

// ---------------- block-sparse attention (flash-style online softmax) ----------------
// grid (NB, H, B); 256 threads; thread (r = tid/4, jq = tid%4) owns query row r,
// score quarter / output-dim quarter jq. Edge blocks (n==0, n==NB-1) attend to all
// 64 key blocks; mid blocks to the 8 gathered blocks {0, n-1, n, n+1, NB-1, r0,r1,r2}.
__global__ void __launch_bounds__(256)
attn_k(const float* __restrict__ Q, const float* __restrict__ K,
       const float* __restrict__ V, const float* __restrict__ mask,
       const int* __restrict__ rb, float* __restrict__ ctx)
{
    __shared__ float ks[64 * 65];   // K tile, then reused for V tile
    __shared__ float ps[64 * 65];   // softmax numerators
    __shared__ float mneg[64];

    const int n  = blockIdx.x;
    const int hh = blockIdx.y;
    const int b  = blockIdx.z;
    const int tid = threadIdx.x;
    const int r  = tid >> 2;
    const int jq = tid & 3;
    const bool edge = (n == 0) || (n == NB_ - 1);
    const int nkb = edge ? NB_ : 8;

    // q row, pre-scaled by 1/sqrt(HD), in registers
    float qreg[64];
    {
        const float* qp = Q + ((size_t)b * S_ + n * 64 + r) * D_ + hh * 64;
#pragma unroll
        for (int i = 0; i < 16; i++) {
            float4 t4 = ((const float4*)qp)[i];
            qreg[4*i+0] = t4.x * 0.125f;
            qreg[4*i+1] = t4.y * 0.125f;
            qreg[4*i+2] = t4.z * 0.125f;
            qreg[4*i+3] = t4.w * 0.125f;
        }
    }
    int rr0 = 0, rr1 = 0, rr2 = 0;
    if (!edge) { rr0 = rb[n*3]; rr1 = rb[n*3+1]; rr2 = rb[n*3+2]; }

    float mrun = -1e30f, lrun = 0.f;
    float o[16];
#pragma unroll
    for (int i = 0; i < 16; i++) o[i] = 0.f;

    for (int t = 0; t < nkb; ++t) {
        int kb;
        if (edge) kb = t;
        else kb = (t == 0) ? 0
                : (t == 1) ? (n - 1)
                : (t == 2) ? n
                : (t == 3) ? (n + 1)
                : (t == 4) ? (NB_ - 1)
                : (t == 5) ? rr0
                : (t == 6) ? rr1 : rr2;

        // load K tile
        {
            const float* kp = K + ((size_t)b * S_ + kb * 64) * D_ + hh * 64;
            for (int idx = tid; idx < 64 * 64; idx += 256) {
                int i = idx >> 6, d = idx & 63;
                ks[i * 65 + d] = kp[(size_t)i * D_ + d];
            }
        }
        if (tid < 64) mneg[tid] = -1e9f * (1.0f - mask[b * S_ + kb * 64 + tid]);
        __syncthreads();

        // scores for this thread's 16 columns
        float sv[16];
        float mloc = -1e30f;
#pragma unroll
        for (int cc = 0; cc < 16; cc++) {
            int c = jq * 16 + cc;
            const float* kr = &ks[c * 65];
            float acc = 0.f;
#pragma unroll
            for (int d = 0; d < 64; d++) acc = fmaf(qreg[d], kr[d], acc);
            acc += mneg[c];
            sv[cc] = acc;
            mloc = fmaxf(mloc, acc);
        }
        mloc = fmaxf(mloc, __shfl_xor_sync(0xffffffffu, mloc, 1));
        mloc = fmaxf(mloc, __shfl_xor_sync(0xffffffffu, mloc, 2));
        float mnew  = fmaxf(mrun, mloc);
        float alpha = __expf(mrun - mnew);
        float lloc = 0.f;
#pragma unroll
        for (int cc = 0; cc < 16; cc++) {
            float p = __expf(sv[cc] - mnew);
            ps[r * 65 + jq * 16 + cc] = p;
            lloc += p;
        }
        lloc += __shfl_xor_sync(0xffffffffu, lloc, 1);
        lloc += __shfl_xor_sync(0xffffffffu, lloc, 2);
        lrun = lrun * alpha + lloc;
        mrun = mnew;
#pragma unroll
        for (int i = 0; i < 16; i++) o[i] *= alpha;
        __syncthreads();   // ps complete; ks reads done

        // load V tile into ks
        {
            const float* vp = V + ((size_t)b * S_ + kb * 64) * D_ + hh * 64;
            for (int idx = tid; idx < 64 * 64; idx += 256) {
                int i = idx >> 6, d = idx & 63;
                ks[i * 65 + d] = vp[(size_t)i * D_ + d];
            }
        }
        __syncthreads();

        const float* pr = &ps[r * 65];
#pragma unroll 16
        for (int c = 0; c < 64; c++) {
            float p = pr[c];
            const float* vr = &ks[c * 65 + jq * 16];
#pragma unroll
            for (int dd = 0; dd < 16; dd++) o[dd] = fmaf(p, vr[dd], o[dd]);
        }
        __syncthreads();   // protect ks/ps for next iteration
    }

    float inv = 1.0f / lrun;
    float* op = ctx + ((size_t)b * S_ + n * 64 + r) * D_ + hh * 64 + jq * 16;
#pragma unroll
    for (int i = 0; i < 4; i++) {
        float4 v4;
        v4.x = o[4*i+0] * inv; v4.y = o[4*i+1] * inv;
        v4.z = o[4*i+2] * inv; v4.w = o[4*i+3] * inv;
        ((float4*)op)[i] = v4;
    }
}

// ---------------- classifier head ----------------
__global__ void cls1_k(const float* __restrict__ h, const float* __restrict__ w1,
                       const float* __restrict__ b1, float* __restrict__ o1)
{
    int idx = blockIdx.x * blockDim.x + threadIdx.x;   // 0..1023
    if (idx >= B_ * 512) return;
    int b = idx >> 9, j = idx & 511;
    const float* row = h + (size_t)b * S_ * D_;        // h[b, 0, :]
    float acc = b1[j];
    for (int d = 0; d < D_; d++) acc = fmaf(row[d], w1[(size_t)d * 512 + j], acc);
    o1[idx] = fmaxf(acc, 0.f);
}

__global__ void cls2_k(const float* __restrict__ c1, const float* __restrict__ w2,
                       const float* __restrict__ b2, float* __restrict__ out)
{
    int idx = blockIdx.x * blockDim.x + threadIdx.x;   // 0..2047
    if (idx >= B_ * TGT_) return;
    int b = idx >> 10, t = idx & 1023;
    float acc = b2[t];
    const float* c = c1 + b * 512;
    for (int d = 0; d < 512; d++) acc = fmaf(c[d], w2[(size_t)d * TGT_ + t], acc);
    out[(size_t)b * TGT_ + t] = acc;
}

// ---------------- launch ----------------
extern "C" void kernel_launch(void* const* d_in, const int* in_sizes, int n_in,
                              void* d_out, int out_size)
{
    const float* x       = (const float*)d_in[0];
    const float* amask   = (const float*)d_in[1];
    const float* proj_w  = (const float*)d_in[2];
    const float* proj_b  = (const float*)d_in[3];
    const float* pos_emb = (const float*)d_in[4];
    const float* tok_emb = (const float*)d_in[5];
    const float* emb_g   = (const float*)d_in[6];
    const float* emb_b   = (const float*)d_in[7];
    const float* wq      = (const float*)d_in[8];
    const float* bq      = (const float*)d_in[9];
    const float* wk      = (const float*)d_in[10];
    const float* bk      = (const float*)d_in[11];
    const float* wv      = (const float*)d_in[12];
    const float* bv      = (const float*)d_in[13];
    const float* wo      = (const float*)d_in[14];
    const float* bo      = (const float*)d_in[15];
    const float* ln1_g   = (const float*)d_in[16];
    const float* ln1_b   = (const float*)d_in[17];
    const float* wi      = (const float*)d_in[18];
    const float* bi      = (const float*)d_in[19];
    const float* wo2     = (const float*)d_in[20];
    const float* bo2     = (const float*)d_in[21];
    const float* ln2_g   = (const float*)d_in[22];
    const float* ln2_b   = (const float*)d_in[23];
    const float* cls_w1  = (const float*)d_in[24];
    const float* cls_b1  = (const float*)d_in[25];
    const float* cls_w2  = (const float*)d_in[26];
    const float* cls_b2  = (const float*)d_in[27];
    const int*   rblk    = (const int*)d_in[28];
    float* out = (float*)d_out;

    float *h, *q, *k, *v, *ctx, *t, *ff, *c1;
    cudaGetSymbolAddress((void**)&h,   g_h);
    cudaGetSymbolAddress((void**)&q,   g_q);
    cudaGetSymbolAddress((void**)&k,   g_k);
    cudaGetSymbolAddress((void**)&v,   g_v);
    cudaGetSymbolAddress((void**)&ctx, g_ctx);
    cudaGetSymbolAddress((void**)&t,   g_t);
    cudaGetSymbolAddress((void**)&ff,  g_ff);
    cudaGetSymbolAddress((void**)&c1,  g_c1);

    const dim3 blk(256);
    const dim3 gD (D_ / 128,  M_ / 128);   // N=768
    const dim3 gFF(FF_ / 128, M_ / 128);   // N=3072

    // input projection + embedding LN
    gemm_bias_k<false><<<gD, blk>>>(x, proj_w, proj_b, t, M_, D_, IN_DIM_);
    emb_ln_k<<<M_, blk>>>(t, pos_emb, tok_emb, emb_g, emb_b, h);

    for (int l = 0; l < L_; ++l) {
        const size_t oDD = (size_t)l * D_ * D_;
        const size_t oD  = (size_t)l * D_;
        const size_t oDF = (size_t)l * D_ * FF_;
        const size_t oF  = (size_t)l * FF_;

        gemm_bias_k<false><<<gD, blk>>>(h, wq + oDD, bq + oD, q, M_, D_, D_);
        gemm_bias_k<false><<<gD, blk>>>(h, wk + oDD, bk + oD, k, M_, D_, D_);
        gemm_bias_k<false><<<gD, blk>>>(h, wv + oDD, bv + oD, v, M_, D_, D_);

        attn_k<<<dim3(NB_, H_, B_), blk>>>(q, k, v, amask, rblk, ctx);

        gemm_bias_k<false><<<gD, blk>>>(ctx, wo + oDD, bo + oD, t, M_, D_, D_);
        ln_res_k<<<M_, blk>>>(h, t, ln1_g + oD, ln1_b + oD);

        gemm_bias_k<true ><<<gFF, blk>>>(h, wi + oDF, bi + oF, ff, M_, FF_, D_);
        gemm_bias_k<false><<<gD,  blk>>>(ff, wo2 + oDF, bo2 + oD, t, M_, D_, FF_);
        ln_res_k<<<M_, blk>>>(h, t, ln2_g + oD, ln2_b + oD);
    }

    cls1_k<<<4, blk>>>(h, cls_w1, cls_b1, c1);
    cls2_k<<<8, blk>>>(c1, cls_w2, cls_b2, out);
}

// round 3
// speedup vs baseline: 3.4511x; 3.4511x over previous
#include <cuda_runtime.h>
#include <math.h>
#include <stdint.h>

// ---------------- problem constants ----------------
#define B_      2
#define S_      4096
#define IN_DIM_ 1280
#define D_      768
#define H_      12
#define HD_     64
#define BS_     64
#define NB_     64
#define FF_     3072
#define L_      12
#define M_      (B_*S_)
#define TGT_    1024

// ---------------- device scratch ----------------
__device__ float g_h  [M_*D_];
__device__ float g_q  [M_*D_];
__device__ float g_k  [M_*D_];
__device__ float g_v  [M_*D_];
__device__ float g_ctx[M_*D_];
__device__ float g_t  [M_*D_];
__device__ float g_ff [M_*FF_];
__device__ float g_c1 [B_*512];
__device__ float g_wt [85917696];   // transposed+rounded+permuted weights (K-major)

#define WT_PROJ   0
#define WT_LBASE  983040
#define WT_LSTRIDE 7077888
#define WT_WQ 0
#define WT_WK 589824
#define WT_WV 1179648
#define WT_WO 1769472
#define WT_WI 2359296
#define WT_WO2 4718592

// ---------------- helpers ----------------
__device__ __forceinline__ float gelu_new(float x) {
    float x3 = x * x * x;
    return 0.5f * x * (1.0f + tanhf(0.7978845608028654f * (x + 0.044715f * x3)));
}
__device__ __forceinline__ uint32_t smem_u32(const void* p) {
    uint32_t a;
    asm("{ .reg .u64 t; cvta.to.shared.u64 t, %1; cvt.u32.u64 %0, t; }" : "=r"(a) : "l"(p));
    return a;
}
__device__ __forceinline__ uint32_t f2tf(float x) {   // round-to-nearest tf32 (bit pattern)
    uint32_t r;
    asm("cvt.rna.tf32.f32 %0, %1;" : "=r"(r) : "f"(x));
    return r;
}
__device__ __forceinline__ void cpa16(uint32_t s, const float* g) {
    asm volatile("cp.async.cg.shared.global [%0], [%1], 16;" :: "r"(s), "l"(g));
}
__device__ __forceinline__ void cpa_commit() {
    asm volatile("cp.async.commit_group;" ::: "memory");
}
__device__ __forceinline__ void cpa_wait1() {
    asm volatile("cp.async.wait_group 1;" ::: "memory");
}
// m16n8k8 tf32 mma, D += A*B
__device__ __forceinline__ void mma8(float* d, const uint32_t* a, uint32_t b0, uint32_t b1) {
    asm volatile(
        "mma.sync.aligned.m16n8k8.row.col.f32.tf32.tf32.f32 "
        "{%0,%1,%2,%3}, {%4,%5,%6,%7}, {%8,%9}, {%0,%1,%2,%3};"
        : "+f"(d[0]), "+f"(d[1]), "+f"(d[2]), "+f"(d[3])
        : "r"(a[0]), "r"(a[1]), "r"(a[2]), "r"(a[3]), "r"(b0), "r"(b1));
}

// ---------------- tensor-core GEMM (mma.sync tf32) ----------------
// C = A(MxK) @ Bt(NxK)^T + bias.  CTA 128x128, BK=32, 3-stage cp.async.
// Bt is pre-rounded to tf32 and k-permuted within 8-groups: [k0,k0+4,k0+1,k0+5,...]
#define BKST 36
#define STAGE_F (128*BKST*2)            // floats per stage (A+B) = 9216
#define GEMM_SMEM (3*STAGE_F*4)         // 110592 bytes

template<bool GELU>
__global__ void __launch_bounds__(256)
gemm_tc(const float* __restrict__ A, const float* __restrict__ Bt,
        const float* __restrict__ bias, float* __restrict__ C,
        int N, int K)
{
    extern __shared__ float sm[];
    uint32_t sbase = smem_u32(sm);
    const int tid = threadIdx.x;
    const int wid = tid >> 5, lane = tid & 31, g = lane >> 2, tg = lane & 3;
    const int wm = (wid >> 1) * 32, wn = (wid & 1) * 64;
    const int m0 = blockIdx.y * 128, n0 = blockIdx.x * 128;
    const int NC = K >> 5;
    const float* Ab = A  + (size_t)m0 * K;
    const float* Bb = Bt + (size_t)n0 * K;

    auto issue = [&](int c, int st) {
        uint32_t sa = sbase + (uint32_t)st * (STAGE_F * 4);
        uint32_t sb = sa + 128 * BKST * 4;
        int k0 = c << 5;
#pragma unroll
        for (int j = 0; j < 4; j++) {
            int u = tid * 4 + j;
            int r = u >> 3, c16 = u & 7;
            cpa16(sa + r * 144 + c16 * 16, Ab + (size_t)r * K + k0 + c16 * 4);
            cpa16(sb + r * 144 + c16 * 16, Bb + (size_t)r * K + k0 + c16 * 4);
        }
    };

    float acc[2][8][4];
#pragma unroll
    for (int mt = 0; mt < 2; mt++)
#pragma unroll
        for (int nt = 0; nt < 8; nt++)
#pragma unroll
            for (int i = 0; i < 4; i++) acc[mt][nt][i] = 0.f;

    issue(0, 0); cpa_commit();
    issue(1, 1); cpa_commit();

    for (int c = 0; c < NC; c++) {
        int st = c % 3;
        cpa_wait1();
        __syncthreads();
        const float* Asp = sm + st * STAGE_F;
        const float* Bsp = Asp + 128 * BKST;
#pragma unroll
        for (int kk = 0; kk < 4; kk++) {
            int k0 = kk * 8;
            uint32_t a[2][4];
#pragma unroll
            for (int mt = 0; mt < 2; mt++) {
                int rb0 = wm + mt * 16;
                a[mt][0] = f2tf(Asp[(rb0 + g)     * BKST + k0 + tg]);
                a[mt][1] = f2tf(Asp[(rb0 + g + 8) * BKST + k0 + tg]);
                a[mt][2] = f2tf(Asp[(rb0 + g)     * BKST + k0 + tg + 4]);
                a[mt][3] = f2tf(Asp[(rb0 + g + 8) * BKST + k0 + tg + 4]);
            }
#pragma unroll
            for (int nt = 0; nt < 8; nt++) {
                float2 bv = *(const float2*)&Bsp[(wn + nt * 8 + g) * BKST + k0 + 2 * tg];
                uint32_t b0 = __float_as_uint(bv.x), b1 = __float_as_uint(bv.y);
                mma8(acc[0][nt], a[0], b0, b1);
                mma8(acc[1][nt], a[1], b0, b1);
            }
        }
        if (c + 2 < NC) issue(c + 2, (c + 2) % 3);
        cpa_commit();
    }

#pragma unroll
    for (int mt = 0; mt < 2; mt++) {
        int rA = m0 + wm + mt * 16 + g;
#pragma unroll
        for (int nt = 0; nt < 8; nt++) {
            int cx = n0 + wn + nt * 8 + 2 * tg;
            float b0f = bias[cx], b1f = bias[cx + 1];
            float v0 = acc[mt][nt][0] + b0f, v1 = acc[mt][nt][1] + b1f;
            float v2 = acc[mt][nt][2] + b0f, v3 = acc[mt][nt][3] + b1f;
            if (GELU) {
                v0 = gelu_new(v0); v1 = gelu_new(v1);
                v2 = gelu_new(v2); v3 = gelu_new(v3);
            }
            float2 lo = make_float2(v0, v1);
            float2 hi = make_float2(v2, v3);
            *(float2*)&C[(size_t)rA * N + cx]       = lo;
            *(float2*)&C[(size_t)(rA + 8) * N + cx] = hi;
        }
    }
}

// ---------------- weight transpose + tf32 round + k-permute ----------------
// out[n][perm(k)] = tf32(in[k][n]); perm within 8-groups: pos = ((k&3)<<1)|((k>>2)&1)
__global__ void transpose_k(const float* __restrict__ in, float* __restrict__ out,
                            int R, int C)
{
    __shared__ float t[32][33];
    int x = blockIdx.x * 32 + threadIdx.x;
    int y0 = blockIdx.y * 32;
#pragma unroll
    for (int i = threadIdx.y; i < 32; i += 8)
        t[i][threadIdx.x] = in[(size_t)(y0 + i) * C + x];
    __syncthreads();
    int ox = y0 + threadIdx.x;                       // original k
    int kperm = (ox & ~7) | ((ox & 3) << 1) | ((ox >> 2) & 1);
    int oy0 = blockIdx.x * 32;
#pragma unroll
    for (int i = threadIdx.y; i < 32; i += 8)
        out[(size_t)(oy0 + i) * R + kperm] = __uint_as_float(f2tf(t[threadIdx.x][i]));
}

// ---------------- LayerNorm ----------------
__device__ __forceinline__ void block_reduce_2(float& s1, float& s2) {
#pragma unroll
    for (int o = 16; o > 0; o >>= 1) {
        s1 += __shfl_xor_sync(0xffffffffu, s1, o);
        s2 += __shfl_xor_sync(0xffffffffu, s2, o);
    }
    __shared__ float sh1[8], sh2[8];
    int w = threadIdx.x >> 5;
    if ((threadIdx.x & 31) == 0) { sh1[w] = s1; sh2[w] = s2; }
    __syncthreads();
    float a = 0.f, b = 0.f;
#pragma unroll
    for (int i = 0; i < 8; i++) { a += sh1[i]; b += sh2[i]; }
    s1 = a; s2 = b;
}

__global__ void emb_ln_k(const float* __restrict__ t, const float* __restrict__ pos,
                         const float* __restrict__ tok, const float* __restrict__ g,
                         const float* __restrict__ be, float* __restrict__ h)
{
    int row = blockIdx.x;
    int s = row & (S_ - 1);
    size_t off = (size_t)row * D_;
    int tid = threadIdx.x;
    float x[3];
#pragma unroll
    for (int e = 0; e < 3; e++) {
        int d = tid + e * 256;
        x[e] = t[off + d] + pos[(size_t)s * D_ + d] + tok[d];
    }
    float s1 = x[0] + x[1] + x[2];
    float s2 = x[0]*x[0] + x[1]*x[1] + x[2]*x[2];
    block_reduce_2(s1, s2);
    float mean = s1 * (1.0f / 768.0f);
    float var  = s2 * (1.0f / 768.0f) - mean * mean;
    float rs = rsqrtf(var + 1e-12f);
#pragma unroll
    for (int e = 0; e < 3; e++) {
        int d = tid + e * 256;
        h[off + d] = (x[e] - mean) * rs * g[d] + be[d];
    }
}

__global__ void ln_res_k(float* __restrict__ h, const float* __restrict__ t,
                         const float* __restrict__ g, const float* __restrict__ be)
{
    int row = blockIdx.x;
    size_t off = (size_t)row * D_;
    int tid = threadIdx.x;
    float x[3];
#pragma unroll
    for (int e = 0; e < 3; e++) {
        int d = tid + e * 256;
        x[e] = h[off + d] + t[off + d];
    }
    float s1 = x[0] + x[1] + x[2];
    float s2 = x[0]*x[0] + x[1]*x[1] + x[2]*x[2];
    block_reduce_2(s1, s2);
    float mean = s1 * (1.0f / 768.0f);
    float var  = s2 * (1.0f / 768.0f) - mean * mean;
    float rs = rsqrtf(var + 1e-12f);
#pragma unroll
    for (int e = 0; e < 3; e++) {
        int d = tid + e * 256;
        h[off + d] = (x[e] - mean) * rs * g[d] + be[d];
    }
}

// ---------------- block-sparse flash attention (mma.sync tf32) ----------------
// 128 threads (4 warps); warp w owns rows 16w..16w+15 of the 64-row Q block.
#define ASTR 68
#define ATTN_SMEM ((4*64*ASTR + 64) * 4)   // qs,ks,vs,ps + mneg = 69888 B

__global__ void __launch_bounds__(128)
attn_k(const float* __restrict__ Q, const float* __restrict__ K,
       const float* __restrict__ V, const float* __restrict__ mask,
       const int* __restrict__ rb, float* __restrict__ ctx)
{
    extern __shared__ float sm[];
    float* qs = sm;
    float* ks = sm + 64 * ASTR;
    float* vs = sm + 2 * 64 * ASTR;
    float* ps = sm + 3 * 64 * ASTR;
    float* mneg = sm + 4 * 64 * ASTR;

    const int n = blockIdx.x, hh = blockIdx.y, b = blockIdx.z;
    const int tid = threadIdx.x, wid = tid >> 5, lane = tid & 31;
    const int g = lane >> 2, tg = lane & 3;
    const int rloc = wid * 16 + g;
    const bool edge = (n == 0) || (n == NB_ - 1);
    const int nkb = edge ? NB_ : 8;

    // load Q (scaled by 1/sqrt(64), tf32-rounded)
    {
        const float* qp = Q + ((size_t)(b * S_) + n * 64) * D_ + hh * 64;
        for (int i = tid; i < 1024; i += 128) {
            int r = i >> 4, c4 = i & 15;
            float4 t4 = *(const float4*)(qp + (size_t)r * D_ + c4 * 4);
            float4 o4;
            o4.x = __uint_as_float(f2tf(t4.x * 0.125f));
            o4.y = __uint_as_float(f2tf(t4.y * 0.125f));
            o4.z = __uint_as_float(f2tf(t4.z * 0.125f));
            o4.w = __uint_as_float(f2tf(t4.w * 0.125f));
            *(float4*)&qs[r * ASTR + c4 * 4] = o4;
        }
    }
    int rr0 = 0, rr1 = 0, rr2 = 0;
    if (!edge) { rr0 = rb[n*3]; rr1 = rb[n*3+1]; rr2 = rb[n*3+2]; }

    float mA = -1e30f, mB = -1e30f, lA = 0.f, lB = 0.f;
    float o[8][4];
#pragma unroll
    for (int nt = 0; nt < 8; nt++)
#pragma unroll
        for (int i = 0; i < 4; i++) o[nt][i] = 0.f;

    for (int t = 0; t < nkb; t++) {
        int kb;
        if (edge) kb = t;
        else kb = (t == 0) ? 0 : (t == 1) ? (n - 1) : (t == 2) ? n
               : (t == 3) ? (n + 1) : (t == 4) ? (NB_ - 1)
               : (t == 5) ? rr0 : (t == 6) ? rr1 : rr2;

        __syncthreads();   // all warps done with previous ks/vs
        {
            const float* kp = K + ((size_t)(b * S_) + kb * 64) * D_ + hh * 64;
            const float* vp = V + ((size_t)(b * S_) + kb * 64) * D_ + hh * 64;
            for (int i = tid; i < 1024; i += 128) {
                int r = i >> 4, c4 = i & 15;
                float4 t4 = *(const float4*)(kp + (size_t)r * D_ + c4 * 4);
                float4 o4;
                o4.x = __uint_as_float(f2tf(t4.x));
                o4.y = __uint_as_float(f2tf(t4.y));
                o4.z = __uint_as_float(f2tf(t4.z));
                o4.w = __uint_as_float(f2tf(t4.w));
                *(float4*)&ks[r * ASTR + c4 * 4] = o4;
                float4 v4 = *(const float4*)(vp + (size_t)r * D_ + c4 * 4);
                float4 w4;
                w4.x = __uint_as_float(f2tf(v4.x));
                w4.y = __uint_as_float(f2tf(v4.y));
                w4.z = __uint_as_float(f2tf(v4.z));
                w4.w = __uint_as_float(f2tf(v4.w));
                *(float4*)&vs[r * ASTR + c4 * 4] = w4;
            }
        }
        if (tid < 64) mneg[tid] = -1e9f * (1.0f - mask[b * S_ + kb * 64 + tid]);
        __syncthreads();

        // S = Q @ K^T
        float s[8][4];
#pragma unroll
        for (int nt = 0; nt < 8; nt++)
#pragma unroll
            for (int i = 0; i < 4; i++) s[nt][i] = 0.f;
#pragma unroll
        for (int k8 = 0; k8 < 8; k8++) {
            int k0 = k8 * 8;
            uint32_t a[4];
            a[0] = __float_as_uint(qs[rloc * ASTR + k0 + tg]);
            a[1] = __float_as_uint(qs[(rloc + 8) * ASTR + k0 + tg]);
            a[2] = __float_as_uint(qs[rloc * ASTR + k0 + tg + 4]);
            a[3] = __float_as_uint(qs[(rloc + 8) * ASTR + k0 + tg + 4]);
#pragma unroll
            for (int nt = 0; nt < 8; nt++) {
                uint32_t b0 = __float_as_uint(ks[(nt * 8 + g) * ASTR + k0 + tg]);
                uint32_t b1 = __float_as_uint(ks[(nt * 8 + g) * ASTR + k0 + tg + 4]);
                mma8(s[nt], a, b0, b1);
            }
        }

        // online softmax (rows rloc, rloc+8; cols 2tg,2tg+1 per n-tile)
        float mxA = -1e30f, mxB = -1e30f;
#pragma unroll
        for (int nt = 0; nt < 8; nt++) {
            int c0 = nt * 8 + 2 * tg;
            s[nt][0] += mneg[c0];     s[nt][1] += mneg[c0 + 1];
            s[nt][2] += mneg[c0];     s[nt][3] += mneg[c0 + 1];
            mxA = fmaxf(mxA, fmaxf(s[nt][0], s[nt][1]));
            mxB = fmaxf(mxB, fmaxf(s[nt][2], s[nt][3]));
        }
        mxA = fmaxf(mxA, __shfl_xor_sync(0xffffffffu, mxA, 1));
        mxA = fmaxf(mxA, __shfl_xor_sync(0xffffffffu, mxA, 2));
        mxB = fmaxf(mxB, __shfl_xor_sync(0xffffffffu, mxB, 1));
        mxB = fmaxf(mxB, __shfl_xor_sync(0xffffffffu, mxB, 2));
        float mnA = fmaxf(mA, mxA), mnB = fmaxf(mB, mxB);
        float aA = __expf(mA - mnA), aB = __expf(mB - mnB);
        float sA = 0.f, sB = 0.f;
#pragma unroll
        for (int nt = 0; nt < 8; nt++) {
            int c0 = nt * 8 + 2 * tg;
            float p0 = __expf(s[nt][0] - mnA), p1 = __expf(s[nt][1] - mnA);
            float p2 = __expf(s[nt][2] - mnB), p3 = __expf(s[nt][3] - mnB);
            sA += p0 + p1; sB += p2 + p3;
            float2 pa = make_float2(__uint_as_float(f2tf(p0)), __uint_as_float(f2tf(p1)));
            float2 pb = make_float2(__uint_as_float(f2tf(p2)), __uint_as_float(f2tf(p3)));
            *(float2*)&ps[rloc * ASTR + c0] = pa;
            *(float2*)&ps[(rloc + 8) * ASTR + c0] = pb;
        }
        sA += __shfl_xor_sync(0xffffffffu, sA, 1);
        sA += __shfl_xor_sync(0xffffffffu, sA, 2);
        sB += __shfl_xor_sync(0xffffffffu, sB, 1);
        sB += __shfl_xor_sync(0xffffffffu, sB, 2);
        lA = lA * aA + sA; lB = lB * aB + sB;
        mA = mnA; mB = mnB;
#pragma unroll
        for (int nt = 0; nt < 8; nt++) {
            o[nt][0] *= aA; o[nt][1] *= aA;
            o[nt][2] *= aB; o[nt][3] *= aB;
        }
        __syncwarp();

        // O += P @ V
#pragma unroll
        for (int k8 = 0; k8 < 8; k8++) {
            int k0 = k8 * 8;
            uint32_t a[4];
            a[0] = __float_as_uint(ps[rloc * ASTR + k0 + tg]);
            a[1] = __float_as_uint(ps[(rloc + 8) * ASTR + k0 + tg]);
            a[2] = __float_as_uint(ps[rloc * ASTR + k0 + tg + 4]);
            a[3] = __float_as_uint(ps[(rloc + 8) * ASTR + k0 + tg + 4]);
#pragma unroll
            for (int nt = 0; nt < 8; nt++) {
                uint32_t b0 = __float_as_uint(vs[(k0 + tg) * ASTR + nt * 8 + g]);
                uint32_t b1 = __float_as_uint(vs[(k0 + tg + 4) * ASTR + nt * 8 + g]);
                mma8(o[nt], a, b0, b1);
            }
        }
    }

    float iA = 1.f / lA, iB = 1.f / lB;
    float* op = ctx + ((size_t)(b * S_) + n * 64) * D_ + hh * 64;
#pragma unroll
    for (int nt = 0; nt < 8; nt++) {
        int c0 = nt * 8 + 2 * tg;
        float2 va = make_float2(o[nt][0] * iA, o[nt][1] * iA);
        float2 vb = make_float2(o[nt][2] * iB, o[nt][3] * iB);
        *(float2*)&op[(size_t)rloc * D_ + c0] = va;
        *(float2*)&op[(size_t)(rloc + 8) * D_ + c0] = vb;
    }
}

// ---------------- classifier head ----------------
__global__ void cls1_k(const float* __restrict__ h, const float* __restrict__ w1,
                       const float* __restrict__ b1, float* __restrict__ o1)
{
    int idx = blockIdx.x * blockDim.x + threadIdx.x;
    if (idx >= B_ * 512) return;
    int b = idx >> 9, j = idx & 511;
    const float* row = h + (size_t)b * S_ * D_;
    float acc = b1[j];
    for (int d = 0; d < D_; d++) acc = fmaf(row[d], w1[(size_t)d * 512 + j], acc);
    o1[idx] = fmaxf(acc, 0.f);
}

__global__ void cls2_k(const float* __restrict__ c1, const float* __restrict__ w2,
                       const float* __restrict__ b2, float* __restrict__ out)
{
    int idx = blockIdx.x * blockDim.x + threadIdx.x;
    if (idx >= B_ * TGT_) return;
    int b = idx >> 10, t = idx & 1023;
    float acc = b2[t];
    const float* c = c1 + b * 512;
    for (int d = 0; d < 512; d++) acc = fmaf(c[d], w2[(size_t)d * TGT_ + t], acc);
    out[(size_t)b * TGT_ + t] = acc;
}

// ---------------- launch ----------------
extern "C" void kernel_launch(void* const* d_in, const int* in_sizes, int n_in,
                              void* d_out, int out_size)
{
    const float* x       = (const float*)d_in[0];
    const float* amask   = (const float*)d_in[1];
    const float* proj_w  = (const float*)d_in[2];
    const float* proj_b  = (const float*)d_in[3];
    const float* pos_emb = (const float*)d_in[4];
    const float* tok_emb = (const float*)d_in[5];
    const float* emb_g   = (const float*)d_in[6];
    const float* emb_b   = (const float*)d_in[7];
    const float* wq      = (const float*)d_in[8];
    const float* bq      = (const float*)d_in[9];
    const float* wk      = (const float*)d_in[10];
    const float* bk      = (const float*)d_in[11];
    const float* wv      = (const float*)d_in[12];
    const float* bv      = (const float*)d_in[13];
    const float* wo      = (const float*)d_in[14];
    const float* bo      = (const float*)d_in[15];
    const float* ln1_g   = (const float*)d_in[16];
    const float* ln1_b   = (const float*)d_in[17];
    const float* wi      = (const float*)d_in[18];
    const float* bi      = (const float*)d_in[19];
    const float* wo2     = (const float*)d_in[20];
    const float* bo2     = (const float*)d_in[21];
    const float* ln2_g   = (const float*)d_in[22];
    const float* ln2_b   = (const float*)d_in[23];
    const float* cls_w1  = (const float*)d_in[24];
    const float* cls_b1  = (const float*)d_in[25];
    const float* cls_w2  = (const float*)d_in[26];
    const float* cls_b2  = (const float*)d_in[27];
    const int*   rblk    = (const int*)d_in[28];
    float* out = (float*)d_out;

    float *h, *q, *k, *v, *ctx, *t, *ff, *c1, *wt;
    cudaGetSymbolAddress((void**)&h,   g_h);
    cudaGetSymbolAddress((void**)&q,   g_q);
    cudaGetSymbolAddress((void**)&k,   g_k);
    cudaGetSymbolAddress((void**)&v,   g_v);
    cudaGetSymbolAddress((void**)&ctx, g_ctx);
    cudaGetSymbolAddress((void**)&t,   g_t);
    cudaGetSymbolAddress((void**)&ff,  g_ff);
    cudaGetSymbolAddress((void**)&c1,  g_c1);
    cudaGetSymbolAddress((void**)&wt,  g_wt);

    cudaFuncSetAttribute(gemm_tc<false>, cudaFuncAttributeMaxDynamicSharedMemorySize, GEMM_SMEM);
    cudaFuncSetAttribute(gemm_tc<true>,  cudaFuncAttributeMaxDynamicSharedMemorySize, GEMM_SMEM);
    cudaFuncSetAttribute(attn_k,         cudaFuncAttributeMaxDynamicSharedMemorySize, ATTN_SMEM);

    const dim3 blk(256);
    const dim3 tb(32, 8);

    // weights -> K-major, tf32-rounded, k-permuted (once per replay)
    transpose_k<<<dim3(D_/32, IN_DIM_/32), tb>>>(proj_w, wt + WT_PROJ, IN_DIM_, D_);
    for (int l = 0; l < L_; ++l) {
        const size_t oDD = (size_t)l * D_ * D_;
        const size_t oDF = (size_t)l * D_ * FF_;
        float* wl = wt + WT_LBASE + (size_t)l * WT_LSTRIDE;
        transpose_k<<<dim3(D_/32,  D_/32),  tb>>>(wq  + oDD, wl + WT_WQ,  D_,  D_);
        transpose_k<<<dim3(D_/32,  D_/32),  tb>>>(wk  + oDD, wl + WT_WK,  D_,  D_);
        transpose_k<<<dim3(D_/32,  D_/32),  tb>>>(wv  + oDD, wl + WT_WV,  D_,  D_);
        transpose_k<<<dim3(D_/32,  D_/32),  tb>>>(wo  + oDD, wl + WT_WO,  D_,  D_);
        transpose_k<<<dim3(FF_/32, D_/32),  tb>>>(wi  + oDF, wl + WT_WI,  D_,  FF_);
        transpose_k<<<dim3(D_/32,  FF_/32), tb>>>(wo2 + oDF, wl + WT_WO2, FF_, D_);
    }

    const dim3 gD (D_ / 128,  M_ / 128);
    const dim3 gFF(FF_ / 128, M_ / 128);

    gemm_tc<false><<<gD, blk, GEMM_SMEM>>>(x, wt + WT_PROJ, proj_b, t, D_, IN_DIM_);
    emb_ln_k<<<M_, blk>>>(t, pos_emb, tok_emb, emb_g, emb_b, h);

    for (int l = 0; l < L_; ++l) {
        const size_t oD = (size_t)l * D_;
        const size_t oF = (size_t)l * FF_;
        float* wl = wt + WT_LBASE + (size_t)l * WT_LSTRIDE;

        gemm_tc<false><<<gD, blk, GEMM_SMEM>>>(h, wl + WT_WQ, bq + oD, q, D_, D_);
        gemm_tc<false><<<gD, blk, GEMM_SMEM>>>(h, wl + WT_WK, bk + oD, k, D_, D_);
        gemm_tc<false><<<gD, blk, GEMM_SMEM>>>(h, wl + WT_WV, bv + oD, v, D_, D_);

        attn_k<<<dim3(NB_, H_, B_), dim3(128), ATTN_SMEM>>>(q, k, v, amask, rblk, ctx);

        gemm_tc<false><<<gD, blk, GEMM_SMEM>>>(ctx, wl + WT_WO, bo + oD, t, D_, D_);
        ln_res_k<<<M_, blk>>>(h, t, ln1_g + oD, ln1_b + oD);

        gemm_tc<true ><<<gFF, blk, GEMM_SMEM>>>(h, wl + WT_WI, bi + oF, ff, FF_, D_);
        gemm_tc<false><<<gD,  blk, GEMM_SMEM>>>(ff, wl + WT_WO2, bo2 + oD, t, D_, FF_);
        ln_res_k<<<M_, blk>>>(h, t, ln2_g + oD, ln2_b + oD);
    }

    cls1_k<<<4, blk>>>(h, cls_w1, cls_b1, c1);
    cls2_k<<<8, blk>>>(c1, cls_w2, cls_b2, out);
}